// round 2
// baseline (speedup 1.0000x reference)
#include <cuda_runtime.h>
#include <cuda_bf16.h>

// Problem dims (fixed per reference)
#define BB 4
#define TT 1024
#define SS 1024
#define CC 1024
#define HH 16
#define DD 64
#define BT (BB * TT)   // 4096

// Scratch buffers (allocation-free rule: __device__ globals)
__device__ float g_Q[BB * HH * TT * DD];     // [B,H,T,D]
__device__ float g_K[BB * HH * SS * DD];     // [B,H,S,D]
__device__ float g_V[BB * HH * SS * DD];     // [B,H,S,D]
__device__ float g_att[BB * TT * HH * DD];   // [B,T,H,D] == [4096, 1024]

// ---------------------------------------------------------------------------
// Projection: Out[b,h,t,d] = sum_c X[b,t,c] * W[h,c,d]
// grid: (BT/64, H), block: 256 threads. 64x64 tile, BK=16, 4x4 microtile.
// ---------------------------------------------------------------------------
__global__ __launch_bounds__(256) void proj_kernel(
    const float* __restrict__ X,   // [BT, C]
    const float* __restrict__ W,   // [H, C, D]
    float* __restrict__ Out)       // [B,H,T,D]
{
    __shared__ float As[16][68];   // [k][m], +4 pad keeps 16B alignment
    __shared__ float Bs[16][68];   // [k][n]

    const int m0 = blockIdx.x * 64;
    const int h  = blockIdx.y;
    const float* Wh = W + (size_t)h * CC * DD;

    const int tid = threadIdx.x;
    const int tx = tid & 15;       // 0..15 -> output cols tx*4..tx*4+3
    const int ty = tid >> 4;       // 0..15 -> output rows ty*4..ty*4+3

    float acc[4][4];
#pragma unroll
    for (int i = 0; i < 4; i++)
#pragma unroll
        for (int j = 0; j < 4; j++) acc[i][j] = 0.f;

    for (int k0 = 0; k0 < CC; k0 += 16) {
#pragma unroll
        for (int i = 0; i < 4; i++) {
            int idx = tid + i * 256;           // 0..1023
            int row = idx >> 4, kk = idx & 15; // A: 64 rows x 16 k
            As[kk][row] = X[(size_t)(m0 + row) * CC + k0 + kk];
        }
#pragma unroll
        for (int i = 0; i < 4; i++) {
            int idx = tid + i * 256;
            int kk = idx >> 6, n = idx & 63;   // B: 16 k x 64 n
            Bs[kk][n] = Wh[(size_t)(k0 + kk) * DD + n];
        }
        __syncthreads();
#pragma unroll
        for (int kk = 0; kk < 16; kk++) {
            float4 a = *reinterpret_cast<const float4*>(&As[kk][ty * 4]);
            float4 b = *reinterpret_cast<const float4*>(&Bs[kk][tx * 4]);
            float av[4] = {a.x, a.y, a.z, a.w};
            float bv[4] = {b.x, b.y, b.z, b.w};
#pragma unroll
            for (int i = 0; i < 4; i++)
#pragma unroll
                for (int j = 0; j < 4; j++) acc[i][j] += av[i] * bv[j];
        }
        __syncthreads();
    }

    // store: Out[((b*H+h)*T + t)*D + n]
#pragma unroll
    for (int i = 0; i < 4; i++) {
        int m = m0 + ty * 4 + i;
        int b = m >> 10;           // /1024
        int t = m & 1023;
        float* op = Out + (((size_t)(b * HH + h) * TT + t) * DD) + tx * 4;
#pragma unroll
        for (int j = 0; j < 4; j++) op[j] = acc[i][j];
    }
}

// ---------------------------------------------------------------------------
// Flash attention per (b,h): 64-query tile per block, online softmax over S.
// grid: (T/64, B*H), block: 256 threads. Thread (r = tid/4, j = tid%4):
//  - scores for keys j*16..j*16+15 of row r
//  - PV accumulation for dims j*16..j*16+15 of row r
// ---------------------------------------------------------------------------
__global__ __launch_bounds__(256) void attn_kernel(
    const float* __restrict__ Q,   // [B,H,T,D]
    const float* __restrict__ K,   // [B,H,S,D]
    const float* __restrict__ V,   // [B,H,S,D]
    float* __restrict__ Oatt)      // [B,T,H,D]
{
    extern __shared__ float sm[];
    float* Qs = sm;                 // [64][65]
    float* Kt = Qs + 64 * 65;       // [64(c)][68]  (transposed K tile)
    float* Vs = Kt + 64 * 68;       // [64(key)][64]
    float* Ps = Vs + 64 * 64;       // [64(q)][65]  (probs)

    const int bh = blockIdx.y;
    const int q0 = blockIdx.x * 64;
    const float* Qb = Q + ((size_t)bh * TT + q0) * DD;
    const float* Kb = K + (size_t)bh * SS * DD;
    const float* Vb = V + (size_t)bh * SS * DD;

    const int tid = threadIdx.x;
    const int r  = tid >> 2;   // query row within tile
    const int j  = tid & 3;
    const int d0 = j * 16;     // also key sub-range base for scores

    // load Q tile (64x64 = 4096 elems)
#pragma unroll
    for (int i = 0; i < 16; i++) {
        int idx = tid + i * 256;       // 0..4095
        int row = idx >> 6, c = idx & 63;
        Qs[row * 65 + c] = Qb[(size_t)row * DD + c];
    }

    float acc[16];
#pragma unroll
    for (int i = 0; i < 16; i++) acc[i] = 0.f;
    float m_i = -1e30f, l_i = 0.f;
    const float scale = 0.03125f;  // C^-0.5 = 1/32

    for (int s0 = 0; s0 < SS; s0 += 64) {
        __syncthreads();   // previous-iter Ps/Vs reads complete (also covers Qs on iter 0)
        // load K/V tiles: 64 keys x 64 dims = 4096 elems each
#pragma unroll
        for (int i = 0; i < 16; i++) {
            int idx = tid + i * 256;       // 0..4095
            int key = idx >> 6, c = idx & 63;
            Kt[c * 68 + key] = Kb[(size_t)(s0 + key) * DD + c];
            Vs[key * 64 + c] = Vb[(size_t)(s0 + key) * DD + c];
        }
        __syncthreads();

        // scores s[i] = q[r] . k[s0 + d0 + i], scaled
        float s[16];
#pragma unroll
        for (int i = 0; i < 16; i++) s[i] = 0.f;
#pragma unroll 8
        for (int c = 0; c < 64; c++) {
            float qv = Qs[r * 65 + c];
            const float4* kp = reinterpret_cast<const float4*>(&Kt[c * 68 + d0]);
            float4 ka = kp[0], kb2 = kp[1], kc2 = kp[2], kd = kp[3];
            s[0]  += qv * ka.x;  s[1]  += qv * ka.y;  s[2]  += qv * ka.z;  s[3]  += qv * ka.w;
            s[4]  += qv * kb2.x; s[5]  += qv * kb2.y; s[6]  += qv * kb2.z; s[7]  += qv * kb2.w;
            s[8]  += qv * kc2.x; s[9]  += qv * kc2.y; s[10] += qv * kc2.z; s[11] += qv * kc2.w;
            s[12] += qv * kd.x;  s[13] += qv * kd.y;  s[14] += qv * kd.z;  s[15] += qv * kd.w;
        }
        float tmax = -1e30f;
#pragma unroll
        for (int i = 0; i < 16; i++) { s[i] *= scale; tmax = fmaxf(tmax, s[i]); }
        // reduce across the 4 threads of this row (consecutive lanes)
        tmax = fmaxf(tmax, __shfl_xor_sync(0xffffffffu, tmax, 1));
        tmax = fmaxf(tmax, __shfl_xor_sync(0xffffffffu, tmax, 2));

        float m_new = fmaxf(m_i, tmax);
        float corr  = __expf(m_i - m_new);
        float psum  = 0.f;
#pragma unroll
        for (int i = 0; i < 16; i++) {
            float p = __expf(s[i] - m_new);
            psum += p;
            Ps[r * 65 + d0 + i] = p;
        }
        psum += __shfl_xor_sync(0xffffffffu, psum, 1);
        psum += __shfl_xor_sync(0xffffffffu, psum, 2);
        l_i = l_i * corr + psum;
        m_i = m_new;
#pragma unroll
        for (int i = 0; i < 16; i++) acc[i] *= corr;

        __syncthreads();   // Ps visible to all threads of the row

        // acc[d0..d0+15] += P[r][k] * V[k][d0..d0+15]
#pragma unroll 8
        for (int k = 0; k < 64; k++) {
            float p = Ps[r * 65 + k];
            const float4* vp = reinterpret_cast<const float4*>(&Vs[k * 64 + d0]);
            float4 va = vp[0], vb2 = vp[1], vc2 = vp[2], vd = vp[3];
            acc[0]  += p * va.x;  acc[1]  += p * va.y;  acc[2]  += p * va.z;  acc[3]  += p * va.w;
            acc[4]  += p * vb2.x; acc[5]  += p * vb2.y; acc[6]  += p * vb2.z; acc[7]  += p * vb2.w;
            acc[8]  += p * vc2.x; acc[9]  += p * vc2.y; acc[10] += p * vc2.z; acc[11] += p * vc2.w;
            acc[12] += p * vd.x;  acc[13] += p * vd.y;  acc[14] += p * vd.z;  acc[15] += p * vd.w;
        }
    }

    float inv = 1.0f / l_i;
    int b  = bh >> 4;
    int h_ = bh & 15;
    int t  = q0 + r;
    float* op = Oatt + (((size_t)(b * TT + t) * HH + h_) * DD) + d0;
#pragma unroll
    for (int i = 0; i < 16; i++) op[i] = acc[i] * inv;
}

// ---------------------------------------------------------------------------
// Output projection: Out[m,n] = sum_k A[m,k] * Wo[n,k] + bo[n]
// grid: (BT/64, C/64), block 256. 64x64 tile, BK=16.
// ---------------------------------------------------------------------------
__global__ __launch_bounds__(256) void outproj_kernel(
    const float* __restrict__ A,    // [4096, 1024] (= g_att)
    const float* __restrict__ Wo,   // [C, C] row-major; used as Wo[n][k]
    const float* __restrict__ bo,   // [C]
    float* __restrict__ Out)        // [4096, 1024]
{
    __shared__ float As[16][68];
    __shared__ float Bs[16][68];

    const int m0 = blockIdx.x * 64;
    const int n0 = blockIdx.y * 64;
    const int tid = threadIdx.x;
    const int tx = tid & 15;
    const int ty = tid >> 4;

    float acc[4][4];
#pragma unroll
    for (int i = 0; i < 4; i++)
#pragma unroll
        for (int j = 0; j < 4; j++) acc[i][j] = 0.f;

    for (int k0 = 0; k0 < CC; k0 += 16) {
#pragma unroll
        for (int i = 0; i < 4; i++) {
            int idx = tid + i * 256;
            int row = idx >> 4, kk = idx & 15;
            As[kk][row] = A[(size_t)(m0 + row) * CC + k0 + kk];
            Bs[kk][row] = Wo[(size_t)(n0 + row) * CC + k0 + kk];
        }
        __syncthreads();
#pragma unroll
        for (int kk = 0; kk < 16; kk++) {
            float4 a = *reinterpret_cast<const float4*>(&As[kk][ty * 4]);
            float4 b = *reinterpret_cast<const float4*>(&Bs[kk][tx * 4]);
            float av[4] = {a.x, a.y, a.z, a.w};
            float bv[4] = {b.x, b.y, b.z, b.w};
#pragma unroll
            for (int i = 0; i < 4; i++)
#pragma unroll
                for (int j = 0; j < 4; j++) acc[i][j] += av[i] * bv[j];
        }
        __syncthreads();
    }

#pragma unroll
    for (int i = 0; i < 4; i++) {
        int m = m0 + ty * 4 + i;
        float* op = Out + (size_t)m * CC + n0 + tx * 4;
#pragma unroll
        for (int j = 0; j < 4; j++) op[j] = acc[i][j] + bo[n0 + tx * 4 + j];
    }
}

// ---------------------------------------------------------------------------
extern "C" void kernel_launch(void* const* d_in, const int* in_sizes, int n_in,
                              void* d_out, int out_size)
{
    const float* x     = (const float*)d_in[0];  // [B,T,C]
    const float* y_enc = (const float*)d_in[1];  // [B,S,C]
    const float* Wq    = (const float*)d_in[2];  // [H,C,D]
    const float* Wk    = (const float*)d_in[3];
    const float* Wv    = (const float*)d_in[4];
    const float* Wo    = (const float*)d_in[5];  // [C,C]
    const float* bo    = (const float*)d_in[6];  // [C]
    float* out = (float*)d_out;

    float *pQ, *pK, *pV, *pA;
    cudaGetSymbolAddress((void**)&pQ, g_Q);
    cudaGetSymbolAddress((void**)&pK, g_K);
    cudaGetSymbolAddress((void**)&pV, g_V);
    cudaGetSymbolAddress((void**)&pA, g_att);

    const int attn_smem = (64 * 65 + 64 * 68 + 64 * 64 + 64 * 65) * (int)sizeof(float);
    cudaFuncSetAttribute(attn_kernel, cudaFuncAttributeMaxDynamicSharedMemorySize,
                         attn_smem);

    dim3 pg(BT / 64, HH);
    proj_kernel<<<pg, 256>>>(x, Wq, pQ);
    proj_kernel<<<pg, 256>>>(y_enc, Wk, pK);
    proj_kernel<<<pg, 256>>>(y_enc, Wv, pV);

    dim3 ag(TT / 64, BB * HH);
    attn_kernel<<<ag, 256, attn_smem>>>(pQ, pK, pV, pA);

    dim3 og(BT / 64, CC / 64);
    outproj_kernel<<<og, 256>>>(pA, Wo, bo, out);
}

// round 3
// speedup vs baseline: 2.3520x; 2.3520x over previous
#include <cuda_runtime.h>

// Problem dims (fixed per reference)
#define BB 4
#define TT 1024
#define SS 1024
#define CC 1024
#define HH 16
#define DD 64
#define BT (BB * TT)   // 4096

// Scratch buffers (allocation-free rule: __device__ globals)
__device__ float g_Q[BB * HH * TT * DD];     // [B,H,T,D]
__device__ float g_K[BB * HH * SS * DD];     // [B,H,S,D]
__device__ float g_V[BB * HH * SS * DD];     // [B,H,S,D]
__device__ float g_att[BB * TT * HH * DD];   // [B,T,H,D] == [4096, 1024]

// ---------------------------------------------------------------------------
// Fused QKV projection: Out[b,h,t,d] = sum_c X[b,t,c] * W[h,c,d]
// grid: (BT/128, HH/2, 3), block 256. Tile 128(m) x 128(n = 2 heads), BK=8.
// 8x8 microtile -> 1 B/FMA shared traffic.
// ---------------------------------------------------------------------------
__global__ __launch_bounds__(256) void qkv_proj_kernel(
    const float* __restrict__ x,     // [BT, C]
    const float* __restrict__ y_enc, // [BT, C]
    const float* __restrict__ Wq, const float* __restrict__ Wk,
    const float* __restrict__ Wv,
    float* __restrict__ Qo, float* __restrict__ Ko, float* __restrict__ Vo)
{
    __shared__ float As[8][132];   // [k][m]
    __shared__ float Bs[8][132];   // [k][n], n in [0,128)

    const int z = blockIdx.z;
    const float* X   = (z == 0) ? x  : y_enc;
    const float* W   = (z == 0) ? Wq : (z == 1) ? Wk : Wv;
    float*       Out = (z == 0) ? Qo : (z == 1) ? Ko : Vo;

    const int m0 = blockIdx.x * 128;
    const int h0 = blockIdx.y * 2;

    const int tid = threadIdx.x;
    const int tx = tid & 15;        // n-block
    const int ty = tid >> 4;        // m-block

    // A load mapping: 128 rows x 8 k = 1024 elems, one float4/thread
    const int arow = tid >> 1;
    const int akq  = (tid & 1) * 4;
    // B load mapping: 8 k x 128 n, one float4/thread
    const int bk = tid >> 5;
    const int bn = (tid & 31) * 4;
    const int bh = h0 + (bn >> 6);
    const int bd = bn & 63;

    const float* Xa = X + (size_t)(m0 + arow) * CC + akq;
    const float* Wb = W + ((size_t)bh * CC + bk) * DD + bd;

    float acc[8][8];
#pragma unroll
    for (int i = 0; i < 8; i++)
#pragma unroll
        for (int j = 0; j < 8; j++) acc[i][j] = 0.f;

    for (int k0 = 0; k0 < CC; k0 += 8) {
        float4 av = *reinterpret_cast<const float4*>(Xa + k0);
        float4 bv = *reinterpret_cast<const float4*>(Wb + (size_t)k0 * DD);
        __syncthreads();
        As[akq + 0][arow] = av.x;
        As[akq + 1][arow] = av.y;
        As[akq + 2][arow] = av.z;
        As[akq + 3][arow] = av.w;
        *reinterpret_cast<float4*>(&Bs[bk][bn]) = bv;
        __syncthreads();
#pragma unroll
        for (int kk = 0; kk < 8; kk++) {
            float4 a0 = *reinterpret_cast<const float4*>(&As[kk][ty * 8]);
            float4 a1 = *reinterpret_cast<const float4*>(&As[kk][ty * 8 + 4]);
            float4 b0 = *reinterpret_cast<const float4*>(&Bs[kk][tx * 4]);
            float4 b1 = *reinterpret_cast<const float4*>(&Bs[kk][64 + tx * 4]);
            float aa[8] = {a0.x, a0.y, a0.z, a0.w, a1.x, a1.y, a1.z, a1.w};
            float bb[8] = {b0.x, b0.y, b0.z, b0.w, b1.x, b1.y, b1.z, b1.w};
#pragma unroll
            for (int i = 0; i < 8; i++)
#pragma unroll
                for (int j = 0; j < 8; j++) acc[i][j] += aa[i] * bb[j];
        }
    }

    // store: cols j<4 -> head h0 at d=tx*4+j ; j>=4 -> head h0+1 at d=tx*4+(j-4)
#pragma unroll
    for (int i = 0; i < 8; i++) {
        int m = m0 + ty * 8 + i;
        int b = m >> 10;
        int t = m & 1023;
        float* o0 = Out + (((size_t)(b * HH + h0)     * TT + t) * DD) + tx * 4;
        float* o1 = Out + (((size_t)(b * HH + h0 + 1) * TT + t) * DD) + tx * 4;
        *reinterpret_cast<float4*>(o0) = make_float4(acc[i][0], acc[i][1], acc[i][2], acc[i][3]);
        *reinterpret_cast<float4*>(o1) = make_float4(acc[i][4], acc[i][5], acc[i][6], acc[i][7]);
    }
}

// ---------------------------------------------------------------------------
// Flash attention: grid (T/128, B*H), block 256.
// Thread (tx = tid&15, ty = tid>>4): 8 query rows (ty*8..) x 4 keys/dims (tx*4..).
// P-row produced & consumed within one warp -> __syncwarp() instead of block sync.
// ---------------------------------------------------------------------------
__global__ __launch_bounds__(256) void attn_kernel(
    const float* __restrict__ Q,   // [B,H,T,D]
    const float* __restrict__ K,   // [B,H,S,D]
    const float* __restrict__ V,   // [B,H,S,D]
    float* __restrict__ Oatt)      // [B,T,H,D]
{
    extern __shared__ float sm[];
    float* Qt = sm;                  // [64 c][132 r]  transposed Q tile
    float* Kt = Qt + 64 * 132;       // [64 c][68 key] transposed K tile
    float* Vs = Kt + 64 * 68;        // [64 key][68 d]
    float* Ps = Vs + 64 * 68;        // [128 q][68 key]

    const int bh = blockIdx.y;
    const int q0 = blockIdx.x * 128;
    const float* Qb = Q + ((size_t)bh * TT + q0) * DD;
    const float* Kb = K + (size_t)bh * SS * DD;
    const float* Vb = V + (size_t)bh * SS * DD;

    const int tid = threadIdx.x;
    const int tx = tid & 15;
    const int ty = tid >> 4;

    // load Q tile transposed: 128 rows x 64 c
#pragma unroll
    for (int p = 0; p < 8; p++) {
        int fq = tid + p * 256;          // 0..2047 float4s
        int row = fq >> 4;               // 0..127
        int cq  = (fq & 15) * 4;
        float4 v = *reinterpret_cast<const float4*>(&Qb[(size_t)row * DD + cq]);
        Qt[(cq + 0) * 132 + row] = v.x;
        Qt[(cq + 1) * 132 + row] = v.y;
        Qt[(cq + 2) * 132 + row] = v.z;
        Qt[(cq + 3) * 132 + row] = v.w;
    }

    float acc[8][4];
#pragma unroll
    for (int i = 0; i < 8; i++)
#pragma unroll
        for (int j = 0; j < 4; j++) acc[i][j] = 0.f;
    float mi[8], li[8];
#pragma unroll
    for (int i = 0; i < 8; i++) { mi[i] = -1e30f; li[i] = 0.f; }
    const float scale = 0.03125f;  // C^-0.5

    for (int s0 = 0; s0 < SS; s0 += 64) {
        __syncthreads();   // prior tile's PV reads / Q visibility
        // K (transposed) + V tiles: 64 keys x 64 c each
#pragma unroll
        for (int p = 0; p < 4; p++) {
            int fq = tid + p * 256;      // 0..1023 float4s
            int key = fq >> 4;           // 0..63
            int cq  = (fq & 15) * 4;
            float4 kv = *reinterpret_cast<const float4*>(&Kb[(size_t)(s0 + key) * DD + cq]);
            Kt[(cq + 0) * 68 + key] = kv.x;
            Kt[(cq + 1) * 68 + key] = kv.y;
            Kt[(cq + 2) * 68 + key] = kv.z;
            Kt[(cq + 3) * 68 + key] = kv.w;
            float4 vv = *reinterpret_cast<const float4*>(&Vb[(size_t)(s0 + key) * DD + cq]);
            *reinterpret_cast<float4*>(&Vs[key * 68 + cq]) = vv;
        }
        __syncthreads();

        // scores: s[i][j] = q[ty*8+i] . k[s0 + tx*4 + j]
        float s[8][4];
#pragma unroll
        for (int i = 0; i < 8; i++)
#pragma unroll
            for (int j = 0; j < 4; j++) s[i][j] = 0.f;
#pragma unroll 8
        for (int c = 0; c < 64; c++) {
            float4 k4 = *reinterpret_cast<const float4*>(&Kt[c * 68 + tx * 4]);
            float4 qa = *reinterpret_cast<const float4*>(&Qt[c * 132 + ty * 8]);
            float4 qb2 = *reinterpret_cast<const float4*>(&Qt[c * 132 + ty * 8 + 4]);
            float qq[8] = {qa.x, qa.y, qa.z, qa.w, qb2.x, qb2.y, qb2.z, qb2.w};
#pragma unroll
            for (int i = 0; i < 8; i++) {
                s[i][0] += qq[i] * k4.x;
                s[i][1] += qq[i] * k4.y;
                s[i][2] += qq[i] * k4.z;
                s[i][3] += qq[i] * k4.w;
            }
        }

        // online softmax per row; reduce across the 16 tx lanes (within warp)
#pragma unroll
        for (int i = 0; i < 8; i++) {
            s[i][0] *= scale; s[i][1] *= scale; s[i][2] *= scale; s[i][3] *= scale;
            float mx = fmaxf(fmaxf(s[i][0], s[i][1]), fmaxf(s[i][2], s[i][3]));
            mx = fmaxf(mx, __shfl_xor_sync(0xffffffffu, mx, 1));
            mx = fmaxf(mx, __shfl_xor_sync(0xffffffffu, mx, 2));
            mx = fmaxf(mx, __shfl_xor_sync(0xffffffffu, mx, 4));
            mx = fmaxf(mx, __shfl_xor_sync(0xffffffffu, mx, 8));
            float mn = fmaxf(mi[i], mx);
            float corr = __expf(mi[i] - mn);
            mi[i] = mn;
            float p0 = __expf(s[i][0] - mn);
            float p1 = __expf(s[i][1] - mn);
            float p2 = __expf(s[i][2] - mn);
            float p3 = __expf(s[i][3] - mn);
            float ps = (p0 + p1) + (p2 + p3);
            ps += __shfl_xor_sync(0xffffffffu, ps, 1);
            ps += __shfl_xor_sync(0xffffffffu, ps, 2);
            ps += __shfl_xor_sync(0xffffffffu, ps, 4);
            ps += __shfl_xor_sync(0xffffffffu, ps, 8);
            li[i] = li[i] * corr + ps;
            acc[i][0] *= corr; acc[i][1] *= corr; acc[i][2] *= corr; acc[i][3] *= corr;
            *reinterpret_cast<float4*>(&Ps[(ty * 8 + i) * 68 + tx * 4]) =
                make_float4(p0, p1, p2, p3);
        }
        __syncwarp();

        // PV: acc[i][j] += sum_key P[row][key] * V[key][tx*4+j]
#pragma unroll 4
        for (int k4i = 0; k4i < 16; k4i++) {
            int key = k4i * 4;
            float4 v0 = *reinterpret_cast<const float4*>(&Vs[(key + 0) * 68 + tx * 4]);
            float4 v1 = *reinterpret_cast<const float4*>(&Vs[(key + 1) * 68 + tx * 4]);
            float4 v2 = *reinterpret_cast<const float4*>(&Vs[(key + 2) * 68 + tx * 4]);
            float4 v3 = *reinterpret_cast<const float4*>(&Vs[(key + 3) * 68 + tx * 4]);
#pragma unroll
            for (int i = 0; i < 8; i++) {
                float4 p4 = *reinterpret_cast<const float4*>(&Ps[(ty * 8 + i) * 68 + key]);
                acc[i][0] += p4.x * v0.x + p4.y * v1.x + p4.z * v2.x + p4.w * v3.x;
                acc[i][1] += p4.x * v0.y + p4.y * v1.y + p4.z * v2.y + p4.w * v3.y;
                acc[i][2] += p4.x * v0.z + p4.y * v1.z + p4.z * v2.z + p4.w * v3.z;
                acc[i][3] += p4.x * v0.w + p4.y * v1.w + p4.z * v2.w + p4.w * v3.w;
            }
        }
        __syncwarp();   // Ps reads done before next tile's stores
    }

    const int b  = bh >> 4;
    const int h_ = bh & 15;
#pragma unroll
    for (int i = 0; i < 8; i++) {
        int t = q0 + ty * 8 + i;
        float inv = 1.0f / li[i];
        float* op = Oatt + (((size_t)(b * TT + t) * HH + h_) * DD) + tx * 4;
        *reinterpret_cast<float4*>(op) =
            make_float4(acc[i][0] * inv, acc[i][1] * inv, acc[i][2] * inv, acc[i][3] * inv);
    }
}

// ---------------------------------------------------------------------------
// Output projection: Out[m,n] = sum_k A[m,k] * Wo[n,k] + bo[n]
// grid: (BT/128, C/128), block 256. 128x128 tile, BK=8, 8x8 microtile.
// ---------------------------------------------------------------------------
__global__ __launch_bounds__(256) void outproj_kernel(
    const float* __restrict__ A,    // [4096, 1024]
    const float* __restrict__ Wo,   // [C, C], used as Wo[n][k]
    const float* __restrict__ bo,   // [C]
    float* __restrict__ Out)        // [4096, 1024]
{
    __shared__ float As[8][132];
    __shared__ float Bs[8][132];

    const int m0 = blockIdx.x * 128;
    const int n0 = blockIdx.y * 128;
    const int tid = threadIdx.x;
    const int tx = tid & 15;
    const int ty = tid >> 4;

    const int arow = tid >> 1;
    const int akq  = (tid & 1) * 4;

    const float* Aa = A  + (size_t)(m0 + arow) * CC + akq;
    const float* Wb = Wo + (size_t)(n0 + arow) * CC + akq;

    float acc[8][8];
#pragma unroll
    for (int i = 0; i < 8; i++)
#pragma unroll
        for (int j = 0; j < 8; j++) acc[i][j] = 0.f;

    for (int k0 = 0; k0 < CC; k0 += 8) {
        float4 av = *reinterpret_cast<const float4*>(Aa + k0);
        float4 bv = *reinterpret_cast<const float4*>(Wb + k0);
        __syncthreads();
        As[akq + 0][arow] = av.x;
        As[akq + 1][arow] = av.y;
        As[akq + 2][arow] = av.z;
        As[akq + 3][arow] = av.w;
        Bs[akq + 0][arow] = bv.x;
        Bs[akq + 1][arow] = bv.y;
        Bs[akq + 2][arow] = bv.z;
        Bs[akq + 3][arow] = bv.w;
        __syncthreads();
#pragma unroll
        for (int kk = 0; kk < 8; kk++) {
            float4 a0 = *reinterpret_cast<const float4*>(&As[kk][ty * 8]);
            float4 a1 = *reinterpret_cast<const float4*>(&As[kk][ty * 8 + 4]);
            float4 b0 = *reinterpret_cast<const float4*>(&Bs[kk][tx * 4]);
            float4 b1 = *reinterpret_cast<const float4*>(&Bs[kk][64 + tx * 4]);
            float aa[8] = {a0.x, a0.y, a0.z, a0.w, a1.x, a1.y, a1.z, a1.w};
            float bb[8] = {b0.x, b0.y, b0.z, b0.w, b1.x, b1.y, b1.z, b1.w};
#pragma unroll
            for (int i = 0; i < 8; i++)
#pragma unroll
                for (int j = 0; j < 8; j++) acc[i][j] += aa[i] * bb[j];
        }
    }

    float4 bias0 = *reinterpret_cast<const float4*>(&bo[n0 + tx * 4]);
    float4 bias1 = *reinterpret_cast<const float4*>(&bo[n0 + 64 + tx * 4]);
#pragma unroll
    for (int i = 0; i < 8; i++) {
        int m = m0 + ty * 8 + i;
        float* o0 = Out + (size_t)m * CC + n0 + tx * 4;
        float* o1 = Out + (size_t)m * CC + n0 + 64 + tx * 4;
        *reinterpret_cast<float4*>(o0) = make_float4(acc[i][0] + bias0.x, acc[i][1] + bias0.y,
                                                     acc[i][2] + bias0.z, acc[i][3] + bias0.w);
        *reinterpret_cast<float4*>(o1) = make_float4(acc[i][4] + bias1.x, acc[i][5] + bias1.y,
                                                     acc[i][6] + bias1.z, acc[i][7] + bias1.w);
    }
}

// ---------------------------------------------------------------------------
extern "C" void kernel_launch(void* const* d_in, const int* in_sizes, int n_in,
                              void* d_out, int out_size)
{
    const float* x     = (const float*)d_in[0];
    const float* y_enc = (const float*)d_in[1];
    const float* Wq    = (const float*)d_in[2];
    const float* Wk    = (const float*)d_in[3];
    const float* Wv    = (const float*)d_in[4];
    const float* Wo    = (const float*)d_in[5];
    const float* bo    = (const float*)d_in[6];
    float* out = (float*)d_out;

    float *pQ, *pK, *pV, *pA;
    cudaGetSymbolAddress((void**)&pQ, g_Q);
    cudaGetSymbolAddress((void**)&pK, g_K);
    cudaGetSymbolAddress((void**)&pV, g_V);
    cudaGetSymbolAddress((void**)&pA, g_att);

    const int attn_smem = (64 * 132 + 64 * 68 + 64 * 68 + 128 * 68) * (int)sizeof(float);
    cudaFuncSetAttribute(attn_kernel, cudaFuncAttributeMaxDynamicSharedMemorySize,
                         attn_smem);

    dim3 pg(BT / 128, HH / 2, 3);
    qkv_proj_kernel<<<pg, 256>>>(x, y_enc, Wq, Wk, Wv, pQ, pK, pV);

    dim3 ag(TT / 128, BB * HH);
    attn_kernel<<<ag, 256, attn_smem>>>(pQ, pK, pV, pA);

    dim3 og(BT / 128, CC / 128);
    outproj_kernel<<<og, 256>>>(pA, Wo, bo, out);
}

// round 4
// speedup vs baseline: 2.4979x; 1.0620x over previous
#include <cuda_runtime.h>

// Problem dims (fixed per reference)
#define BB 4
#define TT 1024
#define SS 1024
#define CC 1024
#define HH 16
#define DD 64
#define BT (BB * TT)   // 4096

// Scratch buffers (allocation-free rule: __device__ globals)
__device__ float g_Q[BB * HH * TT * DD];     // [B,H,T,D]
__device__ float g_K[BB * HH * SS * DD];     // [B,H,S,D]
__device__ float g_V[BB * HH * SS * DD];     // [B,H,S,D]
__device__ float g_att[BB * TT * HH * DD];   // [B,T,H,D] == [4096, 1024]

// ---- packed f32x2 helpers (FFMA2 path; ptxas never emits from C++) --------
__device__ __forceinline__ unsigned long long splat2(float v) {
    unsigned long long r;
    asm("mov.b64 %0, {%1, %1};" : "=l"(r) : "r"(__float_as_uint(v)));
    return r;
}
__device__ __forceinline__ void fma2(unsigned long long& d,
                                     unsigned long long a, unsigned long long b) {
    asm("fma.rn.f32x2 %0, %1, %2, %3;" : "=l"(d) : "l"(a), "l"(b), "l"(d));
}
__device__ __forceinline__ void mul2(unsigned long long& d,
                                     unsigned long long a, unsigned long long b) {
    asm("mul.rn.f32x2 %0, %1, %2;" : "=l"(d) : "l"(a), "l"(b));
}
__device__ __forceinline__ float2 unpack2(unsigned long long p) {
    unsigned int lo, hi;
    asm("mov.b64 {%0, %1}, %2;" : "=r"(lo), "=r"(hi) : "l"(p));
    return make_float2(__uint_as_float(lo), __uint_as_float(hi));
}

// ---------------------------------------------------------------------------
// Fused QKV projection: Out[b,h,t,d] = sum_c X[b,t,c] * W[h,c,d]
// grid: (BT/128, HH/2, 3), block 256. Tile 128(m) x 128(n = 2 heads), BK=8.
// ---------------------------------------------------------------------------
__global__ __launch_bounds__(256) void qkv_proj_kernel(
    const float* __restrict__ x,     // [BT, C]
    const float* __restrict__ y_enc, // [BT, C]
    const float* __restrict__ Wq, const float* __restrict__ Wk,
    const float* __restrict__ Wv,
    float* __restrict__ Qo, float* __restrict__ Ko, float* __restrict__ Vo)
{
    __shared__ float As[8][132];   // [k][m]
    __shared__ float Bs[8][132];   // [k][n]

    const int z = blockIdx.z;
    const float* X   = (z == 0) ? x  : y_enc;
    const float* W   = (z == 0) ? Wq : (z == 1) ? Wk : Wv;
    float*       Out = (z == 0) ? Qo : (z == 1) ? Ko : Vo;

    const int m0 = blockIdx.x * 128;
    const int h0 = blockIdx.y * 2;

    const int tid = threadIdx.x;
    const int tx = tid & 15;
    const int ty = tid >> 4;

    const int arow = tid >> 1;
    const int akq  = (tid & 1) * 4;
    const int bk = tid >> 5;
    const int bn = (tid & 31) * 4;
    const int bh = h0 + (bn >> 6);
    const int bd = bn & 63;

    const float* Xa = X + (size_t)(m0 + arow) * CC + akq;
    const float* Wb = W + ((size_t)bh * CC + bk) * DD + bd;

    unsigned long long acc2[8][4];
#pragma unroll
    for (int i = 0; i < 8; i++)
#pragma unroll
        for (int j = 0; j < 4; j++) acc2[i][j] = 0ull;

    for (int k0 = 0; k0 < CC; k0 += 8) {
        float4 av = *reinterpret_cast<const float4*>(Xa + k0);
        float4 bv = *reinterpret_cast<const float4*>(Wb + (size_t)k0 * DD);
        __syncthreads();
        As[akq + 0][arow] = av.x;
        As[akq + 1][arow] = av.y;
        As[akq + 2][arow] = av.z;
        As[akq + 3][arow] = av.w;
        *reinterpret_cast<float4*>(&Bs[bk][bn]) = bv;
        __syncthreads();
#pragma unroll
        for (int kk = 0; kk < 8; kk++) {
            float4 a0 = *reinterpret_cast<const float4*>(&As[kk][ty * 8]);
            float4 a1 = *reinterpret_cast<const float4*>(&As[kk][ty * 8 + 4]);
            ulonglong2 bp0 = *reinterpret_cast<const ulonglong2*>(&Bs[kk][tx * 4]);
            ulonglong2 bp1 = *reinterpret_cast<const ulonglong2*>(&Bs[kk][64 + tx * 4]);
            unsigned long long bb2[4] = {bp0.x, bp0.y, bp1.x, bp1.y};
            float aa[8] = {a0.x, a0.y, a0.z, a0.w, a1.x, a1.y, a1.z, a1.w};
#pragma unroll
            for (int i = 0; i < 8; i++) {
                unsigned long long as = splat2(aa[i]);
#pragma unroll
                for (int j = 0; j < 4; j++) fma2(acc2[i][j], as, bb2[j]);
            }
        }
    }

#pragma unroll
    for (int i = 0; i < 8; i++) {
        int m = m0 + ty * 8 + i;
        int b = m >> 10;
        int t = m & 1023;
        float2 p0 = unpack2(acc2[i][0]);
        float2 p1 = unpack2(acc2[i][1]);
        float2 p2 = unpack2(acc2[i][2]);
        float2 p3 = unpack2(acc2[i][3]);
        float* o0 = Out + (((size_t)(b * HH + h0)     * TT + t) * DD) + tx * 4;
        float* o1 = Out + (((size_t)(b * HH + h0 + 1) * TT + t) * DD) + tx * 4;
        *reinterpret_cast<float4*>(o0) = make_float4(p0.x, p0.y, p1.x, p1.y);
        *reinterpret_cast<float4*>(o1) = make_float4(p2.x, p2.y, p3.x, p3.y);
    }
}

// ---------------------------------------------------------------------------
// Flash attention: grid (T/128, B*H), block 256.
// Thread (tx = tid&15, ty = tid>>4): 8 query rows x 4 keys/dims.
// ---------------------------------------------------------------------------
__global__ __launch_bounds__(256) void attn_kernel(
    const float* __restrict__ Q,   // [B,H,T,D]
    const float* __restrict__ K,   // [B,H,S,D]
    const float* __restrict__ V,   // [B,H,S,D]
    float* __restrict__ Oatt)      // [B,T,H,D]
{
    extern __shared__ float sm[];
    float* Qt = sm;                  // [64 c][132 r]
    float* Kt = Qt + 64 * 132;       // [64 c][68 key]
    float* Vs = Kt + 64 * 68;        // [64 key][68 d]
    float* Ps = Vs + 64 * 68;        // [128 q][68 key]

    const int bh = blockIdx.y;
    const int q0 = blockIdx.x * 128;
    const float* Qb = Q + ((size_t)bh * TT + q0) * DD;
    const float* Kb = K + (size_t)bh * SS * DD;
    const float* Vb = V + (size_t)bh * SS * DD;

    const int tid = threadIdx.x;
    const int tx = tid & 15;
    const int ty = tid >> 4;

#pragma unroll
    for (int p = 0; p < 8; p++) {
        int fq = tid + p * 256;
        int row = fq >> 4;
        int cq  = (fq & 15) * 4;
        float4 v = *reinterpret_cast<const float4*>(&Qb[(size_t)row * DD + cq]);
        Qt[(cq + 0) * 132 + row] = v.x;
        Qt[(cq + 1) * 132 + row] = v.y;
        Qt[(cq + 2) * 132 + row] = v.z;
        Qt[(cq + 3) * 132 + row] = v.w;
    }

    unsigned long long acc2[8][2];
#pragma unroll
    for (int i = 0; i < 8; i++) { acc2[i][0] = 0ull; acc2[i][1] = 0ull; }
    float mi[8], li[8];
#pragma unroll
    for (int i = 0; i < 8; i++) { mi[i] = -1e30f; li[i] = 0.f; }
    const float scale = 0.03125f;  // C^-0.5

    for (int s0 = 0; s0 < SS; s0 += 64) {
        __syncthreads();
#pragma unroll
        for (int p = 0; p < 4; p++) {
            int fq = tid + p * 256;
            int key = fq >> 4;
            int cq  = (fq & 15) * 4;
            float4 kv = *reinterpret_cast<const float4*>(&Kb[(size_t)(s0 + key) * DD + cq]);
            Kt[(cq + 0) * 68 + key] = kv.x;
            Kt[(cq + 1) * 68 + key] = kv.y;
            Kt[(cq + 2) * 68 + key] = kv.z;
            Kt[(cq + 3) * 68 + key] = kv.w;
            float4 vv = *reinterpret_cast<const float4*>(&Vb[(size_t)(s0 + key) * DD + cq]);
            *reinterpret_cast<float4*>(&Vs[key * 68 + cq]) = vv;
        }
        __syncthreads();

        // scores: s2[i] = pairs over 4 keys (tx*4 .. tx*4+3)
        unsigned long long s2[8][2];
#pragma unroll
        for (int i = 0; i < 8; i++) { s2[i][0] = 0ull; s2[i][1] = 0ull; }
#pragma unroll 8
        for (int c = 0; c < 64; c++) {
            ulonglong2 kp = *reinterpret_cast<const ulonglong2*>(&Kt[c * 68 + tx * 4]);
            float4 qa = *reinterpret_cast<const float4*>(&Qt[c * 132 + ty * 8]);
            float4 qb2 = *reinterpret_cast<const float4*>(&Qt[c * 132 + ty * 8 + 4]);
            float qq[8] = {qa.x, qa.y, qa.z, qa.w, qb2.x, qb2.y, qb2.z, qb2.w};
#pragma unroll
            for (int i = 0; i < 8; i++) {
                unsigned long long qs = splat2(qq[i]);
                fma2(s2[i][0], qs, kp.x);
                fma2(s2[i][1], qs, kp.y);
            }
        }

        // online softmax per row; reduce across 16 tx lanes (within warp)
#pragma unroll
        for (int i = 0; i < 8; i++) {
            float2 sa = unpack2(s2[i][0]);
            float2 sb = unpack2(s2[i][1]);
            float s0v = sa.x * scale, s1v = sa.y * scale;
            float s2v = sb.x * scale, s3v = sb.y * scale;
            float mx = fmaxf(fmaxf(s0v, s1v), fmaxf(s2v, s3v));
            mx = fmaxf(mx, __shfl_xor_sync(0xffffffffu, mx, 1));
            mx = fmaxf(mx, __shfl_xor_sync(0xffffffffu, mx, 2));
            mx = fmaxf(mx, __shfl_xor_sync(0xffffffffu, mx, 4));
            mx = fmaxf(mx, __shfl_xor_sync(0xffffffffu, mx, 8));
            float mn = fmaxf(mi[i], mx);
            float corr = __expf(mi[i] - mn);
            mi[i] = mn;
            float p0 = __expf(s0v - mn);
            float p1 = __expf(s1v - mn);
            float p2 = __expf(s2v - mn);
            float p3 = __expf(s3v - mn);
            float ps = (p0 + p1) + (p2 + p3);
            ps += __shfl_xor_sync(0xffffffffu, ps, 1);
            ps += __shfl_xor_sync(0xffffffffu, ps, 2);
            ps += __shfl_xor_sync(0xffffffffu, ps, 4);
            ps += __shfl_xor_sync(0xffffffffu, ps, 8);
            li[i] = li[i] * corr + ps;
            unsigned long long cs = splat2(corr);
            mul2(acc2[i][0], acc2[i][0], cs);
            mul2(acc2[i][1], acc2[i][1], cs);
            *reinterpret_cast<float4*>(&Ps[(ty * 8 + i) * 68 + tx * 4]) =
                make_float4(p0, p1, p2, p3);
        }
        __syncwarp();

        // PV: acc pairs over dims (tx*4..tx*4+3)
#pragma unroll 4
        for (int k4i = 0; k4i < 16; k4i++) {
            int key = k4i * 4;
            ulonglong2 v0 = *reinterpret_cast<const ulonglong2*>(&Vs[(key + 0) * 68 + tx * 4]);
            ulonglong2 v1 = *reinterpret_cast<const ulonglong2*>(&Vs[(key + 1) * 68 + tx * 4]);
            ulonglong2 v2 = *reinterpret_cast<const ulonglong2*>(&Vs[(key + 2) * 68 + tx * 4]);
            ulonglong2 v3 = *reinterpret_cast<const ulonglong2*>(&Vs[(key + 3) * 68 + tx * 4]);
#pragma unroll
            for (int i = 0; i < 8; i++) {
                float4 p4 = *reinterpret_cast<const float4*>(&Ps[(ty * 8 + i) * 68 + key]);
                unsigned long long ps0 = splat2(p4.x);
                fma2(acc2[i][0], ps0, v0.x);
                fma2(acc2[i][1], ps0, v0.y);
                unsigned long long ps1 = splat2(p4.y);
                fma2(acc2[i][0], ps1, v1.x);
                fma2(acc2[i][1], ps1, v1.y);
                unsigned long long ps2 = splat2(p4.z);
                fma2(acc2[i][0], ps2, v2.x);
                fma2(acc2[i][1], ps2, v2.y);
                unsigned long long ps3 = splat2(p4.w);
                fma2(acc2[i][0], ps3, v3.x);
                fma2(acc2[i][1], ps3, v3.y);
            }
        }
        __syncwarp();
    }

    const int b  = bh >> 4;
    const int h_ = bh & 15;
#pragma unroll
    for (int i = 0; i < 8; i++) {
        int t = q0 + ty * 8 + i;
        float inv = 1.0f / li[i];
        float2 a0 = unpack2(acc2[i][0]);
        float2 a1 = unpack2(acc2[i][1]);
        float* op = Oatt + (((size_t)(b * TT + t) * HH + h_) * DD) + tx * 4;
        *reinterpret_cast<float4*>(op) =
            make_float4(a0.x * inv, a0.y * inv, a1.x * inv, a1.y * inv);
    }
}

// ---------------------------------------------------------------------------
// Output projection: Out[m,n] = sum_k A[m,k] * Wo[n,k] + bo[n]
// grid: (BT/128, C/128), block 256. 128x128 tile, BK=8, 8x8 microtile.
// ---------------------------------------------------------------------------
__global__ __launch_bounds__(256) void outproj_kernel(
    const float* __restrict__ A,    // [4096, 1024]
    const float* __restrict__ Wo,   // [C, C], used as Wo[n][k]
    const float* __restrict__ bo,   // [C]
    float* __restrict__ Out)        // [4096, 1024]
{
    __shared__ float As[8][132];
    __shared__ float Bs[8][132];

    const int m0 = blockIdx.x * 128;
    const int n0 = blockIdx.y * 128;
    const int tid = threadIdx.x;
    const int tx = tid & 15;
    const int ty = tid >> 4;

    const int arow = tid >> 1;
    const int akq  = (tid & 1) * 4;

    const float* Aa = A  + (size_t)(m0 + arow) * CC + akq;
    const float* Wb = Wo + (size_t)(n0 + arow) * CC + akq;

    unsigned long long acc2[8][4];
#pragma unroll
    for (int i = 0; i < 8; i++)
#pragma unroll
        for (int j = 0; j < 4; j++) acc2[i][j] = 0ull;

    for (int k0 = 0; k0 < CC; k0 += 8) {
        float4 av = *reinterpret_cast<const float4*>(Aa + k0);
        float4 bv = *reinterpret_cast<const float4*>(Wb + k0);
        __syncthreads();
        As[akq + 0][arow] = av.x;
        As[akq + 1][arow] = av.y;
        As[akq + 2][arow] = av.z;
        As[akq + 3][arow] = av.w;
        Bs[akq + 0][arow] = bv.x;
        Bs[akq + 1][arow] = bv.y;
        Bs[akq + 2][arow] = bv.z;
        Bs[akq + 3][arow] = bv.w;
        __syncthreads();
#pragma unroll
        for (int kk = 0; kk < 8; kk++) {
            float4 a0 = *reinterpret_cast<const float4*>(&As[kk][ty * 8]);
            float4 a1 = *reinterpret_cast<const float4*>(&As[kk][ty * 8 + 4]);
            ulonglong2 bp0 = *reinterpret_cast<const ulonglong2*>(&Bs[kk][tx * 4]);
            ulonglong2 bp1 = *reinterpret_cast<const ulonglong2*>(&Bs[kk][64 + tx * 4]);
            unsigned long long bb2[4] = {bp0.x, bp0.y, bp1.x, bp1.y};
            float aa[8] = {a0.x, a0.y, a0.z, a0.w, a1.x, a1.y, a1.z, a1.w};
#pragma unroll
            for (int i = 0; i < 8; i++) {
                unsigned long long as = splat2(aa[i]);
#pragma unroll
                for (int j = 0; j < 4; j++) fma2(acc2[i][j], as, bb2[j]);
            }
        }
    }

    float4 bias0 = *reinterpret_cast<const float4*>(&bo[n0 + tx * 4]);
    float4 bias1 = *reinterpret_cast<const float4*>(&bo[n0 + 64 + tx * 4]);
#pragma unroll
    for (int i = 0; i < 8; i++) {
        int m = m0 + ty * 8 + i;
        float2 p0 = unpack2(acc2[i][0]);
        float2 p1 = unpack2(acc2[i][1]);
        float2 p2 = unpack2(acc2[i][2]);
        float2 p3 = unpack2(acc2[i][3]);
        float* o0 = Out + (size_t)m * CC + n0 + tx * 4;
        float* o1 = Out + (size_t)m * CC + n0 + 64 + tx * 4;
        *reinterpret_cast<float4*>(o0) = make_float4(p0.x + bias0.x, p0.y + bias0.y,
                                                     p1.x + bias0.z, p1.y + bias0.w);
        *reinterpret_cast<float4*>(o1) = make_float4(p2.x + bias1.x, p2.y + bias1.y,
                                                     p3.x + bias1.z, p3.y + bias1.w);
    }
}

// ---------------------------------------------------------------------------
extern "C" void kernel_launch(void* const* d_in, const int* in_sizes, int n_in,
                              void* d_out, int out_size)
{
    const float* x     = (const float*)d_in[0];
    const float* y_enc = (const float*)d_in[1];
    const float* Wq    = (const float*)d_in[2];
    const float* Wk    = (const float*)d_in[3];
    const float* Wv    = (const float*)d_in[4];
    const float* Wo    = (const float*)d_in[5];
    const float* bo    = (const float*)d_in[6];
    float* out = (float*)d_out;

    float *pQ, *pK, *pV, *pA;
    cudaGetSymbolAddress((void**)&pQ, g_Q);
    cudaGetSymbolAddress((void**)&pK, g_K);
    cudaGetSymbolAddress((void**)&pV, g_V);
    cudaGetSymbolAddress((void**)&pA, g_att);

    const int attn_smem = (64 * 132 + 64 * 68 + 64 * 68 + 128 * 68) * (int)sizeof(float);
    cudaFuncSetAttribute(attn_kernel, cudaFuncAttributeMaxDynamicSharedMemorySize,
                         attn_smem);

    dim3 pg(BT / 128, HH / 2, 3);
    qkv_proj_kernel<<<pg, 256>>>(x, y_enc, Wq, Wk, Wv, pQ, pK, pV);

    dim3 ag(TT / 128, BB * HH);
    attn_kernel<<<ag, 256, attn_smem>>>(pQ, pK, pV, pA);

    dim3 og(BT / 128, CC / 128);
    outproj_kernel<<<og, 256>>>(pA, Wo, bo, out);
}